// round 2
// baseline (speedup 1.0000x reference)
#include <cuda_runtime.h>
#include <math.h>

// Problem dims (fixed by the reference)
#define TT 8192      // B*S tokens
#define DD 2048      // emb dim
#define EE 8         // experts
#define MM 1024      // intermediate
#define ROWCAP (2*TT + EE*128)   // 17408 padded dispatch rows

// ---------------- device scratch (static globals: no allocation) ----------------
__device__ int   g_cnt[EE];
__device__ int   g_cur[EE];
__device__ int   g_start[EE];
__device__ int   g_size[EE];
__device__ int   g_e0[TT];
__device__ int   g_e1[TT];
__device__ float g_w0[TT];
__device__ float g_w1[TT];
__device__ int   g_tok[ROWCAP];
__device__ float g_rw[ROWCAP];
__device__ float g_inter[(size_t)ROWCAP * MM];   // ~71 MB scratch

// ---------------- init ----------------
__global__ void k_zero_out(float* out, int n4) {
    int i = blockIdx.x * blockDim.x + threadIdx.x;
    int stride = gridDim.x * blockDim.x;
    float4 z = make_float4(0.f, 0.f, 0.f, 0.f);
    for (int j = i; j < n4; j += stride) ((float4*)out)[j] = z;
}

__global__ void k_zero_cnt() {
    int i = threadIdx.x;
    if (i < EE) { g_cnt[i] = 0; g_cur[i] = 0; }
}

// ---------------- routing: warp per token ----------------
__global__ void k_route(const float* __restrict__ x, const float* __restrict__ wg) {
    int gw   = (blockIdx.x * blockDim.x + threadIdx.x) >> 5;
    int lane = threadIdx.x & 31;
    if (gw >= TT) return;
    const float* xr = x + (size_t)gw * DD;

    float acc[EE];
#pragma unroll
    for (int e = 0; e < EE; e++) acc[e] = 0.f;

    for (int d = lane; d < DD; d += 32) {
        float xv = xr[d];
        const float* w = wg + d * EE;
#pragma unroll
        for (int e = 0; e < EE; e++) acc[e] += xv * w[e];
    }
#pragma unroll
    for (int e = 0; e < EE; e++) {
#pragma unroll
        for (int off = 16; off > 0; off >>= 1)
            acc[e] += __shfl_xor_sync(0xffffffffu, acc[e], off);
    }

    if (lane == 0) {
        float l0 = -1e30f; int e0 = 0;
#pragma unroll
        for (int e = 0; e < EE; e++) if (acc[e] > l0) { l0 = acc[e]; e0 = e; }
        float l1 = -1e30f; int e1 = 0;
#pragma unroll
        for (int e = 0; e < EE; e++) if (e != e0 && acc[e] > l1) { l1 = acc[e]; e1 = e; }
        // softmax over {l0, l1}, l0 is the max
        float s1 = expf(l1 - l0);
        float w0 = 1.f / (1.f + s1);
        float w1 = s1 * w0;
        g_e0[gw] = e0; g_e1[gw] = e1; g_w0[gw] = w0; g_w1[gw] = w1;
        atomicAdd(&g_cnt[e0], 1);
        atomicAdd(&g_cnt[e1], 1);
    }
}

// ---------------- group offsets (tiny) ----------------
__global__ void k_offsets() {
    if (threadIdx.x == 0 && blockIdx.x == 0) {
        int o = 0;
        for (int e = 0; e < EE; e++) {
            g_start[e] = o;
            int c = g_cnt[e];
            g_size[e]  = c;
            o += (c + 127) & ~127;   // 128-row padding per expert
        }
    }
}

// ---------------- scatter: build dispatch permutation ----------------
__global__ void k_scatter() {
    int t = blockIdx.x * blockDim.x + threadIdx.x;
    if (t >= TT) return;
    int e = g_e0[t];
    int p = g_start[e] + atomicAdd(&g_cur[e], 1);
    g_tok[p] = t; g_rw[p] = g_w0[t];
    e = g_e1[t];
    p = g_start[e] + atomicAdd(&g_cur[e], 1);
    g_tok[p] = t; g_rw[p] = g_w1[t];
}

// ---------------- GEMM1: inter = silu(x@wi0[e]) * (x@wi1[e]), gathered rows ----------------
// block tile 128(M rows) x 64(N cols), BK=16, 256 threads, micro 8x4 per matrix
__global__ void __launch_bounds__(256) k_gemm1(const float* __restrict__ x,
                                               const float* __restrict__ wi0,
                                               const float* __restrict__ wi1) {
    int e    = blockIdx.z;
    int size = g_size[e];
    int m0   = blockIdx.y * 128;
    if (m0 >= size) return;
    int n0    = blockIdx.x * 64;
    int start = g_start[e];

    __shared__ float As[16][128];
    __shared__ float B0s[16][64];
    __shared__ float B1s[16][64];
    __shared__ int   stok[128];

    int tid = threadIdx.x;
    if (tid < 128) {
        int r = m0 + tid;
        stok[tid] = (r < size) ? g_tok[start + r] : -1;
    }
    __syncthreads();

    const float* wb0 = wi0 + (size_t)e * DD * MM + n0;
    const float* wb1 = wi1 + (size_t)e * DD * MM + n0;

    float acc0[8][4], acc1[8][4];
#pragma unroll
    for (int i = 0; i < 8; i++)
#pragma unroll
        for (int j = 0; j < 4; j++) { acc0[i][j] = 0.f; acc1[i][j] = 0.f; }

    int ty = tid >> 4, tx = tid & 15;
    int ar = tid >> 1;            // A row (0..127)
    int ah = (tid & 1) * 8;       // A k-half (0 or 8)
    int bk = tid >> 4;            // B k row (0..15)
    int bn = (tid & 15) * 4;      // B col seg
    int atok = stok[ar];
    const float* abase = (atok >= 0) ? (x + (size_t)atok * DD + ah) : x;

    for (int k0 = 0; k0 < DD; k0 += 16) {
        float4 a0 = make_float4(0.f,0.f,0.f,0.f), a1 = a0;
        if (atok >= 0) {
            const float4* p = (const float4*)(abase + k0);
            a0 = p[0]; a1 = p[1];
        }
        float4 b0v = *(const float4*)(wb0 + (size_t)(k0 + bk) * MM + bn);
        float4 b1v = *(const float4*)(wb1 + (size_t)(k0 + bk) * MM + bn);
        __syncthreads();
        As[ah+0][ar] = a0.x; As[ah+1][ar] = a0.y; As[ah+2][ar] = a0.z; As[ah+3][ar] = a0.w;
        As[ah+4][ar] = a1.x; As[ah+5][ar] = a1.y; As[ah+6][ar] = a1.z; As[ah+7][ar] = a1.w;
        *(float4*)&B0s[bk][bn] = b0v;
        *(float4*)&B1s[bk][bn] = b1v;
        __syncthreads();
#pragma unroll
        for (int k = 0; k < 16; k++) {
            float a[8];
            *(float4*)&a[0] = *(const float4*)&As[k][ty * 8];
            *(float4*)&a[4] = *(const float4*)&As[k][ty * 8 + 4];
            float4 b0 = *(const float4*)&B0s[k][tx * 4];
            float4 b1 = *(const float4*)&B1s[k][tx * 4];
#pragma unroll
            for (int i = 0; i < 8; i++) {
                acc0[i][0] += a[i] * b0.x; acc0[i][1] += a[i] * b0.y;
                acc0[i][2] += a[i] * b0.z; acc0[i][3] += a[i] * b0.w;
                acc1[i][0] += a[i] * b1.x; acc1[i][1] += a[i] * b1.y;
                acc1[i][2] += a[i] * b1.z; acc1[i][3] += a[i] * b1.w;
            }
        }
    }

#pragma unroll
    for (int i = 0; i < 8; i++) {
        int r = m0 + ty * 8 + i;
        if (r < size) {
            float4 v;
            float h0, h1, s;
            h0 = acc0[i][0]; h1 = acc1[i][0]; s = h0 / (1.f + expf(-h0)); v.x = s * h1;
            h0 = acc0[i][1]; h1 = acc1[i][1]; s = h0 / (1.f + expf(-h0)); v.y = s * h1;
            h0 = acc0[i][2]; h1 = acc1[i][2]; s = h0 / (1.f + expf(-h0)); v.z = s * h1;
            h0 = acc0[i][3]; h1 = acc1[i][3]; s = h0 / (1.f + expf(-h0)); v.w = s * h1;
            *(float4*)&g_inter[(size_t)(start + r) * MM + n0 + tx * 4] = v;
        }
    }
}

// ---------------- GEMM2: out[tok] += w * (inter @ wo[e]) ----------------
// block tile 128 x 128, BK=8, 256 threads, micro 8x8
__global__ void __launch_bounds__(256) k_gemm2(const float* __restrict__ wo,
                                               float* __restrict__ out) {
    int e    = blockIdx.z;
    int size = g_size[e];
    int m0   = blockIdx.y * 128;
    if (m0 >= size) return;
    int n0    = blockIdx.x * 128;
    int start = g_start[e];

    __shared__ float As[8][128];
    __shared__ float Bs[8][128];
    __shared__ int   stok[128];
    __shared__ float sw[128];

    int tid = threadIdx.x;
    if (tid < 128) {
        int r = m0 + tid;
        bool v = (r < size);
        stok[tid] = v ? g_tok[start + r] : -1;
        sw[tid]   = v ? g_rw[start + r]  : 0.f;
    }
    __syncthreads();

    const float* wb = wo + (size_t)e * MM * DD + n0;

    float acc[8][8];
#pragma unroll
    for (int i = 0; i < 8; i++)
#pragma unroll
        for (int j = 0; j < 8; j++) acc[i][j] = 0.f;

    int ty = tid >> 4, tx = tid & 15;
    int ar   = tid >> 1;          // A row (0..127)
    int aseg = (tid & 1) * 4;     // A k seg (0 or 4)
    int bk   = tid >> 5;          // B k row (0..7)
    int bn   = (tid & 31) * 4;    // B col seg
    bool avalid = (stok[ar] >= 0);
    const float* arowp = &g_inter[(size_t)(start + m0 + ar) * MM + aseg];

    for (int k0 = 0; k0 < MM; k0 += 8) {
        float4 av = make_float4(0.f,0.f,0.f,0.f);
        if (avalid) av = *(const float4*)(arowp + k0);
        float4 bv = *(const float4*)(wb + (size_t)(k0 + bk) * DD + bn);
        __syncthreads();
        As[aseg+0][ar] = av.x; As[aseg+1][ar] = av.y;
        As[aseg+2][ar] = av.z; As[aseg+3][ar] = av.w;
        *(float4*)&Bs[bk][bn] = bv;
        __syncthreads();
#pragma unroll
        for (int k = 0; k < 8; k++) {
            float a[8], b[8];
            *(float4*)&a[0] = *(const float4*)&As[k][ty * 8];
            *(float4*)&a[4] = *(const float4*)&As[k][ty * 8 + 4];
            *(float4*)&b[0] = *(const float4*)&Bs[k][tx * 8];
            *(float4*)&b[4] = *(const float4*)&Bs[k][tx * 8 + 4];
#pragma unroll
            for (int i = 0; i < 8; i++)
#pragma unroll
                for (int j = 0; j < 8; j++) acc[i][j] += a[i] * b[j];
        }
    }

    // epilogue: weighted scatter-add (exactly 2 adds per out element -> deterministic)
#pragma unroll
    for (int i = 0; i < 8; i++) {
        int rr  = ty * 8 + i;
        int tok = stok[rr];
        if (tok >= 0) {
            float w = sw[rr];
            float* dst = out + (size_t)tok * DD + n0 + tx * 8;
#pragma unroll
            for (int j = 0; j < 8; j++) atomicAdd(dst + j, w * acc[i][j]);
        }
    }
}

// ---------------- launch ----------------
extern "C" void kernel_launch(void* const* d_in, const int* in_sizes, int n_in,
                              void* d_out, int out_size) {
    const float* x   = (const float*)d_in[0];   // [T, D]
    const float* wg  = (const float*)d_in[1];   // [D, E]
    const float* wi0 = (const float*)d_in[2];   // [E, D, M]
    const float* wi1 = (const float*)d_in[3];   // [E, D, M]
    const float* wo  = (const float*)d_in[4];   // [E, M, D]
    float* out = (float*)d_out;                 // [T, D]

    (void)in_sizes; (void)n_in; (void)out_size;

    k_zero_out<<<2048, 256>>>(out, (TT * DD) / 4);
    k_zero_cnt<<<1, 32>>>();
    k_route<<<TT / 8, 256>>>(x, wg);
    k_offsets<<<1, 32>>>();
    k_scatter<<<TT / 256, 256>>>();

    dim3 g1(MM / 64, 64, EE);    // cols, worst-case row tiles (8192/128), experts
    k_gemm1<<<g1, 256>>>(x, wi0, wi1);

    dim3 g2(DD / 128, 64, EE);
    k_gemm2<<<g2, 256>>>(wo, out);
}